// round 2
// baseline (speedup 1.0000x reference)
#include <cuda_runtime.h>
#include <math.h>

// ---------------- problem constants ----------------
#define NPTS_MAX 200000
#define NB_MAX   220000          // 4*220*250
#define NC_MAX   98304           // 4*512*48
#define IMG_ELEMS (4*512*48*64)  // dense cyl image, [B][512][48][64]

#define CVS0 (6.2831853f/512.0f)
#define CVS1 0.125f
#define CR0  (-3.14159265f)
#define CR1  (-2.0f)

// ---------------- scratch (static device memory; no allocs) ----------------
__device__ float d_lin1[(size_t)NPTS_MAX*64];   // lin1 pre-BN, later reused for lin3 pre-BN
__device__ float d_lin2[(size_t)NPTS_MAX*128];  // lin2 pre-BN
__device__ float d_dense[IMG_ELEMS];            // cyl max image (post bn2-relu), channel-last
__device__ float d_conv[IMG_ELEMS];             // conv output pre-BN, channel-last
__device__ float d_bevsum[NB_MAX*4];            // sum x,y,z + count
__device__ float d_cylsum[NC_MAX*4];            // sum phi,z,rho + count
__device__ float d_stats[1024];                 // bases: lin1 0, lin2 128, conv 384, lin3 512
__device__ float d_bn[1024];                    // same bases: a then c per stage

// ---------------- kernels ----------------
__global__ void k_scatter(const float* __restrict__ pts, const float* __restrict__ pcyl,
                          const int* __restrict__ binv, const int* __restrict__ cinv, int n) {
    int i = blockIdx.x*blockDim.x + threadIdx.x;
    if (i >= n) return;
    float x = pts[(size_t)i*5+1], y = pts[(size_t)i*5+2], z = pts[(size_t)i*5+3];
    int bi = binv[i], ci = cinv[i];
    atomicAdd(&d_bevsum[bi*4+0], x);
    atomicAdd(&d_bevsum[bi*4+1], y);
    atomicAdd(&d_bevsum[bi*4+2], z);
    atomicAdd(&d_bevsum[bi*4+3], 1.0f);
    float p0 = pcyl[(size_t)i*3], p1 = pcyl[(size_t)i*3+1], p2 = pcyl[(size_t)i*3+2];
    atomicAdd(&d_cylsum[ci*4+0], p0);
    atomicAdd(&d_cylsum[ci*4+1], p1);
    atomicAdd(&d_cylsum[ci*4+2], p2);
    atomicAdd(&d_cylsum[ci*4+3], 1.0f);
}

__global__ void __launch_bounds__(256) k_lin1(
        const float* __restrict__ pts, const float* __restrict__ pcyl,
        const float* __restrict__ cylidx, const float* __restrict__ bevidx,
        const int* __restrict__ binv, const int* __restrict__ cinv,
        const float* __restrict__ w1, int n) {
    __shared__ float sw[16*64];   // sw[k*64+o] = w1[o*16+k]
    for (int t = threadIdx.x; t < 1024; t += 256) { int o = t >> 4, k = t & 15; sw[k*64+o] = w1[t]; }
    __syncthreads();
    int i = blockIdx.x*256 + threadIdx.x;
    if (i >= n) return;
    float x = pts[(size_t)i*5+1], y = pts[(size_t)i*5+2], z = pts[(size_t)i*5+3], it = pts[(size_t)i*5+4];
    float phi = pcyl[(size_t)i*3], zc = pcyl[(size_t)i*3+1], rho = pcyl[(size_t)i*3+2];
    float bix = bevidx[2*(size_t)i], biy = bevidx[2*(size_t)i+1];
    float cix = cylidx[2*(size_t)i], ciy = cylidx[2*(size_t)i+1];
    int bi = binv[i], ci = cinv[i];
    float bcnt = d_bevsum[bi*4+3];
    float bmx = d_bevsum[bi*4]/bcnt, bmy = d_bevsum[bi*4+1]/bcnt;
    float ccnt = d_cylsum[ci*4+3];
    float cm0 = d_cylsum[ci*4]/ccnt, cm1 = d_cylsum[ci*4+1]/ccnt;
    float f[16];
    f[0]=x; f[1]=y; f[2]=z; f[3]=phi; f[4]=zc; f[5]=rho;
    f[6] = x - ((floorf(bix)+0.5f)*0.32f + 0.0f);
    f[7] = y - ((floorf(biy)+0.5f)*0.32f + (-40.0f));
    f[8] = phi - ((floorf(cix)+0.5f)*CVS0 + CR0);
    f[9] = zc  - ((floorf(ciy)+0.5f)*CVS1 + CR1);
    f[10]= x - bmx; f[11]= y - bmy;
    f[12]= phi - cm0; f[13]= zc - cm1;
    f[14]= sqrtf(x*x + y*y + z*z);
    f[15]= it;
    float acc[64];
    #pragma unroll
    for (int o = 0; o < 64; o++) acc[o] = 0.f;
    #pragma unroll
    for (int k = 0; k < 16; k++) {
        float v = f[k];
        #pragma unroll
        for (int o4 = 0; o4 < 16; o4++) {
            float4 w = *(const float4*)&sw[k*64 + o4*4];
            acc[4*o4+0] += v*w.x; acc[4*o4+1] += v*w.y;
            acc[4*o4+2] += v*w.z; acc[4*o4+3] += v*w.w;
        }
    }
    float4* op = (float4*)&d_lin1[(size_t)i*64];
    #pragma unroll
    for (int o4 = 0; o4 < 16; o4++)
        op[o4] = make_float4(acc[4*o4], acc[4*o4+1], acc[4*o4+2], acc[4*o4+3]);
}

// generic per-channel sum/sumsq over [rows x C] (C power of two)
__global__ void k_stats(const float* __restrict__ data, int rows, int C, int shift, float* __restrict__ out) {
    int tid = threadIdx.x;
    int c = tid & (C-1);
    int sub = tid >> shift;
    int rpb = 256 >> shift;
    float s = 0.f, s2 = 0.f;
    for (long r = (long)blockIdx.x*rpb + sub; r < rows; r += (long)gridDim.x*rpb) {
        float v = data[(size_t)r*C + c];
        s += v; s2 += v*v;
    }
    __shared__ float sh[512];
    sh[tid] = s; sh[256+tid] = s2;
    __syncthreads();
    if (sub == 0) {
        for (int j = 1; j < rpb; j++) { s += sh[j*C + c]; s2 += sh[256 + j*C + c]; }
        atomicAdd(&out[c], s);
        atomicAdd(&out[C+c], s2);
    }
}

__global__ void k_finalize(const float* __restrict__ g, const float* __restrict__ b,
                           int C, float invn, int sbase, int bbase) {
    int c = threadIdx.x;
    if (c < C) {
        float m = d_stats[sbase+c]*invn;
        float v = d_stats[sbase+C+c]*invn - m*m;
        float a = g[c]*rsqrtf(v + 1e-3f);
        d_bn[bbase+c]   = a;
        d_bn[bbase+C+c] = b[c] - m*a;
    }
}

// lin2: h = bn_relu(lin1), out = h @ w2^T  (64 -> 128). 2 threads per point.
__global__ void __launch_bounds__(256) k_lin2(const float* __restrict__ w2, int n) {
    __shared__ float sw[64*128];   // sw[k*128+o] = w2[o*64+k]
    __shared__ float sa[64], sc[64];
    for (int t = threadIdx.x; t < 8192; t += 256) { int o = t >> 6, k = t & 63; sw[k*128+o] = w2[t]; }
    if (threadIdx.x < 64) { sa[threadIdx.x] = d_bn[threadIdx.x]; sc[threadIdx.x] = d_bn[64+threadIdx.x]; }
    __syncthreads();
    int gi = blockIdx.x*256 + threadIdx.x;
    int p = gi >> 1, half = gi & 1;
    if (p >= n) return;
    const float4* h4 = (const float4*)&d_lin1[(size_t)p*64];
    float acc[64];
    #pragma unroll
    for (int o = 0; o < 64; o++) acc[o] = 0.f;
    #pragma unroll 4
    for (int kk = 0; kk < 16; kk++) {
        float4 hv = h4[kk];
        int kb = kk*4;
        float v0 = fmaxf(fmaf(hv.x, sa[kb+0], sc[kb+0]), 0.f);
        float v1 = fmaxf(fmaf(hv.y, sa[kb+1], sc[kb+1]), 0.f);
        float v2 = fmaxf(fmaf(hv.z, sa[kb+2], sc[kb+2]), 0.f);
        float v3 = fmaxf(fmaf(hv.w, sa[kb+3], sc[kb+3]), 0.f);
        float vv[4] = {v0, v1, v2, v3};
        #pragma unroll
        for (int j = 0; j < 4; j++) {
            float v = vv[j];
            const float4* wr = (const float4*)&sw[(kb+j)*128 + half*64];
            #pragma unroll
            for (int o4 = 0; o4 < 16; o4++) {
                float4 w = wr[o4];
                acc[4*o4+0] += v*w.x; acc[4*o4+1] += v*w.y;
                acc[4*o4+2] += v*w.z; acc[4*o4+3] += v*w.w;
            }
        }
    }
    float4* op = (float4*)&d_lin2[(size_t)p*128 + half*64];
    #pragma unroll
    for (int o4 = 0; o4 < 16; o4++)
        op[o4] = make_float4(acc[4*o4], acc[4*o4+1], acc[4*o4+2], acc[4*o4+3]);
}

// segment-max of bn_relu(lin2[:, :64]) scattered into dense image (atomicMax on nonneg floats)
__global__ void k_cylmax(const float* __restrict__ pts, const float* __restrict__ cylidx, int n) {
    __shared__ float sa[64], sc[64];
    if (threadIdx.x < 64) { sa[threadIdx.x] = d_bn[128+threadIdx.x]; sc[threadIdx.x] = d_bn[256+threadIdx.x]; }
    __syncthreads();
    int i = blockIdx.x*blockDim.x + threadIdx.x;
    if (i >= n) return;
    int b = (int)pts[(size_t)i*5];
    int iy = (int)floorf(cylidx[2*(size_t)i]);   iy = max(0, min(iy, 511));
    int ix = (int)floorf(cylidx[2*(size_t)i+1]); ix = max(0, min(ix, 47));
    unsigned* dst = (unsigned*)&d_dense[(((size_t)b*512 + iy)*48 + ix)*64];
    const float4* src = (const float4*)&d_lin2[(size_t)i*128];
    #pragma unroll
    for (int j = 0; j < 16; j++) {
        float4 v = src[j];
        int c = j*4;
        float r0 = fmaxf(fmaf(v.x, sa[c+0], sc[c+0]), 0.f);
        float r1 = fmaxf(fmaf(v.y, sa[c+1], sc[c+1]), 0.f);
        float r2 = fmaxf(fmaf(v.z, sa[c+2], sc[c+2]), 0.f);
        float r3 = fmaxf(fmaf(v.w, sa[c+3], sc[c+3]), 0.f);
        atomicMax(dst+c+0, __float_as_uint(r0));
        atomicMax(dst+c+1, __float_as_uint(r1));
        atomicMax(dst+c+2, __float_as_uint(r2));
        atomicMax(dst+c+3, __float_as_uint(r3));
    }
}

// 3x3 SAME conv, 64->64 ch, input d_dense [B][512][48][64], output d_conv (pre-BN)
#define CTY 4
#define CTX 16
#define CHALO ((CTY+2)*(CTX+2))   // 108
#define CPITCH 65
__global__ void __launch_bounds__(256) k_conv(const float* __restrict__ wc) {
    __shared__ float s_in[CHALO*CPITCH];   // ~28KB
    __shared__ float s_w[64*64];           // 16KB: s_w[cin*64+f]
    int x0 = blockIdx.x*CTX, y0 = blockIdx.y*CTY, bb = blockIdx.z;
    int tid = threadIdx.x;
    for (int idx = tid; idx < CHALO*16; idx += 256) {
        int pos = idx >> 4, c4 = idx & 15;
        int hy = pos / (CTX+2), hx = pos % (CTX+2);
        int gy = y0 + hy - 1, gx = x0 + hx - 1;
        float4 v = make_float4(0.f,0.f,0.f,0.f);
        if (gy >= 0 && gy < 512 && gx >= 0 && gx < 48)
            v = *(const float4*)&d_dense[(((size_t)bb*512 + gy)*48 + gx)*64 + c4*4];
        float* s = &s_in[pos*CPITCH + c4*4];
        s[0]=v.x; s[1]=v.y; s[2]=v.z; s[3]=v.w;
    }
    int fs = tid >> 5;           // 0..7 (8 channels each)
    int ps = tid & 31;           // 32 position slots (2 positions each)
    int ly0 = ps >> 4, lx = ps & 15;
    float a0[8], a1[8];
    #pragma unroll
    for (int j = 0; j < 8; j++) { a0[j]=0.f; a1[j]=0.f; }
    for (int tap = 0; tap < 9; tap++) {
        int dy = tap/3, dx = tap%3;
        __syncthreads();
        for (int idx = tid; idx < 4096; idx += 256) {
            int cin = idx >> 6, f = idx & 63;
            s_w[idx] = wc[((size_t)f*64 + cin)*9 + tap];
        }
        __syncthreads();
        int h0 = ((ly0+dy)*(CTX+2) + lx + dx)*CPITCH;
        int h1 = ((ly0+2+dy)*(CTX+2) + lx + dx)*CPITCH;
        #pragma unroll 8
        for (int cin = 0; cin < 64; cin++) {
            float i0 = s_in[h0+cin], i1 = s_in[h1+cin];
            float4 wA = *(const float4*)&s_w[cin*64 + fs*8];
            float4 wB = *(const float4*)&s_w[cin*64 + fs*8 + 4];
            a0[0]+=i0*wA.x; a0[1]+=i0*wA.y; a0[2]+=i0*wA.z; a0[3]+=i0*wA.w;
            a0[4]+=i0*wB.x; a0[5]+=i0*wB.y; a0[6]+=i0*wB.z; a0[7]+=i0*wB.w;
            a1[0]+=i1*wA.x; a1[1]+=i1*wA.y; a1[2]+=i1*wA.z; a1[3]+=i1*wA.w;
            a1[4]+=i1*wB.x; a1[5]+=i1*wB.y; a1[6]+=i1*wB.z; a1[7]+=i1*wB.w;
        }
    }
    int gx = x0 + lx;
    {
        int gy = y0 + ly0;
        float* o = &d_conv[(((size_t)bb*512 + gy)*48 + gx)*64 + fs*8];
        *(float4*)&o[0] = make_float4(a0[0],a0[1],a0[2],a0[3]);
        *(float4*)&o[4] = make_float4(a0[4],a0[5],a0[6],a0[7]);
    }
    {
        int gy = y0 + ly0 + 2;
        float* o = &d_conv[(((size_t)bb*512 + gy)*48 + gx)*64 + fs*8];
        *(float4*)&o[0] = make_float4(a1[0],a1[1],a1[2],a1[3]);
        *(float4*)&o[4] = make_float4(a1[4],a1[5],a1[6],a1[7]);
    }
}

// lin3: mvf2 = [bn_relu(lin2[:,64:]), bilinear(bn_relu(conv))] @ w3^T -> d_lin1 (pre-BN)
__global__ void __launch_bounds__(128) k_lin3(const float* __restrict__ pts,
        const float* __restrict__ cylidx, const float* __restrict__ w3, int n) {
    __shared__ float sw[128*64];   // sw[k*64+o] = w3[o*128+k]
    __shared__ float pa[64], pc[64], ca[64], cs[64];
    for (int t = threadIdx.x; t < 8192; t += 128) { int o = t >> 7, k = t & 127; sw[k*64+o] = w3[t]; }
    if (threadIdx.x < 64) {
        int c = threadIdx.x;
        pa[c] = d_bn[192+c]; pc[c] = d_bn[320+c];   // bn2 channels 64..127
        ca[c] = d_bn[384+c]; cs[c] = d_bn[448+c];   // conv bn
    }
    __syncthreads();
    int i = blockIdx.x*128 + threadIdx.x;
    if (i >= n) return;
    float yq = cylidx[2*(size_t)i], xq = cylidx[2*(size_t)i+1];
    int y0 = (int)floorf(yq); int y1 = min(y0+1, 511); y0 = min(max(y0,0), 511);
    int x0 = (int)floorf(xq); int x1 = min(x0+1, 47);  x0 = min(max(x0,0), 47);
    float wa = ((float)x1 - xq)*((float)y1 - yq);
    float wb = ((float)x1 - xq)*(yq - (float)y0);
    float wcw= (xq - (float)x0)*((float)y1 - yq);
    float wd = (xq - (float)x0)*(yq - (float)y0);
    int b = (int)pts[(size_t)i*5];
    size_t base = (size_t)b*512*48*64;
    const float4* A = (const float4*)&d_conv[base + ((size_t)y0*48 + x0)*64];
    const float4* Bp= (const float4*)&d_conv[base + ((size_t)y1*48 + x0)*64];
    const float4* Cp= (const float4*)&d_conv[base + ((size_t)y0*48 + x1)*64];
    const float4* Dp= (const float4*)&d_conv[base + ((size_t)y1*48 + x1)*64];
    const float4* pw= (const float4*)&d_lin2[(size_t)i*128 + 64];
    float acc[64];
    #pragma unroll
    for (int o = 0; o < 64; o++) acc[o] = 0.f;
    // pointwise half (inputs k = 0..63)
    #pragma unroll 4
    for (int kk = 0; kk < 16; kk++) {
        float4 t = pw[kk];
        int c = kk*4;
        float vv[4];
        vv[0] = fmaxf(fmaf(t.x, pa[c+0], pc[c+0]), 0.f);
        vv[1] = fmaxf(fmaf(t.y, pa[c+1], pc[c+1]), 0.f);
        vv[2] = fmaxf(fmaf(t.z, pa[c+2], pc[c+2]), 0.f);
        vv[3] = fmaxf(fmaf(t.w, pa[c+3], pc[c+3]), 0.f);
        #pragma unroll
        for (int j = 0; j < 4; j++) {
            float v = vv[j];
            const float4* wr = (const float4*)&sw[(c+j)*64];
            #pragma unroll
            for (int o4 = 0; o4 < 16; o4++) {
                float4 w = wr[o4];
                acc[4*o4+0] += v*w.x; acc[4*o4+1] += v*w.y;
                acc[4*o4+2] += v*w.z; acc[4*o4+3] += v*w.w;
            }
        }
    }
    // bilinear half (inputs k = 64..127)
    #pragma unroll 2
    for (int kk = 0; kk < 16; kk++) {
        int c = kk*4;
        float4 av = A[kk], bv = Bp[kk], cv = Cp[kk], dv = Dp[kk];
        float vv[4];
        vv[0] = wa*fmaxf(fmaf(av.x, ca[c+0], cs[c+0]),0.f) + wb*fmaxf(fmaf(bv.x, ca[c+0], cs[c+0]),0.f)
              + wcw*fmaxf(fmaf(cv.x, ca[c+0], cs[c+0]),0.f) + wd*fmaxf(fmaf(dv.x, ca[c+0], cs[c+0]),0.f);
        vv[1] = wa*fmaxf(fmaf(av.y, ca[c+1], cs[c+1]),0.f) + wb*fmaxf(fmaf(bv.y, ca[c+1], cs[c+1]),0.f)
              + wcw*fmaxf(fmaf(cv.y, ca[c+1], cs[c+1]),0.f) + wd*fmaxf(fmaf(dv.y, ca[c+1], cs[c+1]),0.f);
        vv[2] = wa*fmaxf(fmaf(av.z, ca[c+2], cs[c+2]),0.f) + wb*fmaxf(fmaf(bv.z, ca[c+2], cs[c+2]),0.f)
              + wcw*fmaxf(fmaf(cv.z, ca[c+2], cs[c+2]),0.f) + wd*fmaxf(fmaf(dv.z, ca[c+2], cs[c+2]),0.f);
        vv[3] = wa*fmaxf(fmaf(av.w, ca[c+3], cs[c+3]),0.f) + wb*fmaxf(fmaf(bv.w, ca[c+3], cs[c+3]),0.f)
              + wcw*fmaxf(fmaf(cv.w, ca[c+3], cs[c+3]),0.f) + wd*fmaxf(fmaf(dv.w, ca[c+3], cs[c+3]),0.f);
        #pragma unroll
        for (int j = 0; j < 4; j++) {
            float v = vv[j];
            const float4* wr = (const float4*)&sw[(64+c+j)*64];
            #pragma unroll
            for (int o4 = 0; o4 < 16; o4++) {
                float4 w = wr[o4];
                acc[4*o4+0] += v*w.x; acc[4*o4+1] += v*w.y;
                acc[4*o4+2] += v*w.z; acc[4*o4+3] += v*w.w;
            }
        }
    }
    float4* op = (float4*)&d_lin1[(size_t)i*64];
    #pragma unroll
    for (int o4 = 0; o4 < 16; o4++)
        op[o4] = make_float4(acc[4*o4], acc[4*o4+1], acc[4*o4+2], acc[4*o4+3]);
}

// final: mvf_fea = bn_relu(lin3) -> out[0:N*64]; atomicMax into bev_max region
__global__ void k_final(const int* __restrict__ binv, float* __restrict__ out, int n, int nb) {
    __shared__ float sa[64], sc[64];
    if (threadIdx.x < 64) { sa[threadIdx.x] = d_bn[512+threadIdx.x]; sc[threadIdx.x] = d_bn[576+threadIdx.x]; }
    __syncthreads();
    int i = blockIdx.x*blockDim.x + threadIdx.x;
    if (i >= n) return;
    int bi = binv[i];
    const float4* src = (const float4*)&d_lin1[(size_t)i*64];
    float4* dst = (float4*)(out + (size_t)i*64);
    unsigned* mx = (unsigned*)(out + (size_t)n*64 + (size_t)bi*64);
    #pragma unroll
    for (int j = 0; j < 16; j++) {
        float4 v = src[j];
        int c = j*4;
        float r0 = fmaxf(fmaf(v.x, sa[c+0], sc[c+0]), 0.f);
        float r1 = fmaxf(fmaf(v.y, sa[c+1], sc[c+1]), 0.f);
        float r2 = fmaxf(fmaf(v.z, sa[c+2], sc[c+2]), 0.f);
        float r3 = fmaxf(fmaf(v.w, sa[c+3], sc[c+3]), 0.f);
        dst[j] = make_float4(r0, r1, r2, r3);
        atomicMax(mx+c+0, __float_as_uint(r0));
        atomicMax(mx+c+1, __float_as_uint(r1));
        atomicMax(mx+c+2, __float_as_uint(r2));
        atomicMax(mx+c+3, __float_as_uint(r3));
    }
}

__global__ void k_voxel(const int* __restrict__ coords, float* __restrict__ out, int n, int nb) {
    int i = blockIdx.x*blockDim.x + threadIdx.x;
    if (i >= nb) return;
    int c = coords[i];
    int vb = c / 55000;
    int r  = c % 55000;
    int vx = r / 250;
    int vy = r % 250;
    float* o = out + (size_t)n*64 + (size_t)nb*64 + (size_t)i*4;
    o[0] = (float)vb; o[1] = 0.f; o[2] = (float)vy; o[3] = (float)vx;
}

// ---------------- launcher ----------------
extern "C" void kernel_launch(void* const* d_in, const int* in_sizes, int n_in,
                              void* d_out, int out_size) {
    const float* points = (const float*)d_in[0];
    const float* pcyl   = (const float*)d_in[1];
    const float* cylidx = (const float*)d_in[2];
    const float* bevidx = (const float*)d_in[3];
    const float* w1 = (const float*)d_in[4];
    const float* g1 = (const float*)d_in[5];
    const float* b1 = (const float*)d_in[6];
    const float* w2 = (const float*)d_in[7];
    const float* g2 = (const float*)d_in[8];
    const float* b2 = (const float*)d_in[9];
    const float* wc = (const float*)d_in[10];
    const float* gc = (const float*)d_in[11];
    const float* bc = (const float*)d_in[12];
    const float* w3 = (const float*)d_in[13];
    const float* g3 = (const float*)d_in[14];
    const float* b3 = (const float*)d_in[15];
    const int* binv   = (const int*)d_in[16];
    const int* bcoord = (const int*)d_in[17];
    const int* cinv   = (const int*)d_in[18];

    int n  = in_sizes[0] / 5;
    int nb = in_sizes[17];
    int nc = in_sizes[19];
    float* out = (float*)d_out;

    void *p_lin1, *p_lin2, *p_conv, *p_dense, *p_bevsum, *p_cylsum, *p_stats;
    cudaGetSymbolAddress(&p_lin1, d_lin1);
    cudaGetSymbolAddress(&p_lin2, d_lin2);
    cudaGetSymbolAddress(&p_conv, d_conv);
    cudaGetSymbolAddress(&p_dense, d_dense);
    cudaGetSymbolAddress(&p_bevsum, d_bevsum);
    cudaGetSymbolAddress(&p_cylsum, d_cylsum);
    cudaGetSymbolAddress(&p_stats, d_stats);

    cudaMemsetAsync(p_bevsum, 0, (size_t)nb*4*sizeof(float));
    cudaMemsetAsync(p_cylsum, 0, (size_t)nc*4*sizeof(float));
    cudaMemsetAsync(p_dense, 0, (size_t)IMG_ELEMS*sizeof(float));
    cudaMemsetAsync(p_stats, 0, 1024*sizeof(float));
    cudaMemsetAsync(out + (size_t)n*64, 0, (size_t)nb*64*sizeof(float));

    int nblk = (n + 255) / 256;
    k_scatter<<<nblk, 256>>>(points, pcyl, binv, cinv, n);
    k_lin1<<<nblk, 256>>>(points, pcyl, cylidx, bevidx, binv, cinv, w1, n);
    k_stats<<<512, 256>>>((const float*)p_lin1, n, 64, 6, (float*)p_stats + 0);
    k_finalize<<<1, 128>>>(g1, b1, 64, 1.0f/(float)n, 0, 0);
    k_lin2<<<(2*n + 255)/256, 256>>>(w2, n);
    k_stats<<<512, 256>>>((const float*)p_lin2, n, 128, 7, (float*)p_stats + 128);
    k_finalize<<<1, 128>>>(g2, b2, 128, 1.0f/(float)n, 128, 128);
    k_cylmax<<<nblk, 256>>>(points, cylidx, n);
    dim3 cg(3, 128, 4);
    k_conv<<<cg, 256>>>(wc);
    k_stats<<<512, 256>>>((const float*)p_conv, 4*512*48, 64, 6, (float*)p_stats + 384);
    k_finalize<<<1, 128>>>(gc, bc, 64, 1.0f/(float)(4*512*48), 384, 384);
    k_lin3<<<(n + 127)/128, 128>>>(points, cylidx, w3, n);
    k_stats<<<512, 256>>>((const float*)p_lin1, n, 64, 6, (float*)p_stats + 512);
    k_finalize<<<1, 128>>>(g3, b3, 64, 1.0f/(float)n, 512, 512);
    k_final<<<nblk, 256>>>(binv, out, n, nb);
    k_voxel<<<(nb + 255)/256, 256>>>(bcoord, out, n, nb);
}

// round 3
// speedup vs baseline: 1.3260x; 1.3260x over previous
#include <cuda_runtime.h>
#include <math.h>

typedef unsigned long long ull;

// ---------------- problem constants ----------------
#define NPTS_MAX 200000
#define NB_MAX   220000
#define NC_MAX   98304
#define IMG_ELEMS (4*512*48*64)

#define CVS0 (6.2831853f/512.0f)
#define CVS1 0.125f
#define CR0  (-3.14159265f)
#define CR1  (-2.0f)

// ---------------- scratch ----------------
__device__ float d_lin1[(size_t)NPTS_MAX*64];
__device__ float d_lin2[(size_t)NPTS_MAX*128];
__device__ float d_dense[IMG_ELEMS];
__device__ float d_conv[IMG_ELEMS];
__device__ float d_bevsum[NB_MAX*4];
__device__ float d_cylsum[NC_MAX*4];
__device__ float d_stats[1024];
__device__ float d_bn[1024];

// ---------------- f32x2 helpers ----------------
__device__ __forceinline__ ull pk2(float v) {
    ull r; unsigned u = __float_as_uint(v);
    asm("mov.b64 %0, {%1, %1};" : "=l"(r) : "r"(u));
    return r;
}
__device__ __forceinline__ void ffma2(ull& d, ull a, ull b) {
    asm("fma.rn.f32x2 %0, %1, %2, %0;" : "+l"(d) : "l"(a), "l"(b));
}

// ---------------- kernels ----------------
__global__ void k_scatter(const float* __restrict__ pts, const float* __restrict__ pcyl,
                          const int* __restrict__ binv, const int* __restrict__ cinv, int n) {
    int i = blockIdx.x*blockDim.x + threadIdx.x;
    if (i >= n) return;
    float x = pts[(size_t)i*5+1], y = pts[(size_t)i*5+2], z = pts[(size_t)i*5+3];
    int bi = binv[i], ci = cinv[i];
    atomicAdd(&d_bevsum[bi*4+0], x);
    atomicAdd(&d_bevsum[bi*4+1], y);
    atomicAdd(&d_bevsum[bi*4+2], z);
    atomicAdd(&d_bevsum[bi*4+3], 1.0f);
    float p0 = pcyl[(size_t)i*3], p1 = pcyl[(size_t)i*3+1], p2 = pcyl[(size_t)i*3+2];
    atomicAdd(&d_cylsum[ci*4+0], p0);
    atomicAdd(&d_cylsum[ci*4+1], p1);
    atomicAdd(&d_cylsum[ci*4+2], p2);
    atomicAdd(&d_cylsum[ci*4+3], 1.0f);
}

__global__ void __launch_bounds__(256) k_lin1(
        const float* __restrict__ pts, const float* __restrict__ pcyl,
        const float* __restrict__ cylidx, const float* __restrict__ bevidx,
        const int* __restrict__ binv, const int* __restrict__ cinv,
        const float* __restrict__ w1, int n) {
    __shared__ float sw[16*64];
    for (int t = threadIdx.x; t < 1024; t += 256) { int o = t >> 4, k = t & 15; sw[k*64+o] = w1[t]; }
    __syncthreads();
    int i = blockIdx.x*256 + threadIdx.x;
    if (i >= n) return;
    float x = pts[(size_t)i*5+1], y = pts[(size_t)i*5+2], z = pts[(size_t)i*5+3], it = pts[(size_t)i*5+4];
    float phi = pcyl[(size_t)i*3], zc = pcyl[(size_t)i*3+1], rho = pcyl[(size_t)i*3+2];
    float bix = bevidx[2*(size_t)i], biy = bevidx[2*(size_t)i+1];
    float cix = cylidx[2*(size_t)i], ciy = cylidx[2*(size_t)i+1];
    int bi = binv[i], ci = cinv[i];
    float bcnt = d_bevsum[bi*4+3];
    float bmx = d_bevsum[bi*4]/bcnt, bmy = d_bevsum[bi*4+1]/bcnt;
    float ccnt = d_cylsum[ci*4+3];
    float cm0 = d_cylsum[ci*4]/ccnt, cm1 = d_cylsum[ci*4+1]/ccnt;
    float f[16];
    f[0]=x; f[1]=y; f[2]=z; f[3]=phi; f[4]=zc; f[5]=rho;
    f[6] = x - ((floorf(bix)+0.5f)*0.32f + 0.0f);
    f[7] = y - ((floorf(biy)+0.5f)*0.32f + (-40.0f));
    f[8] = phi - ((floorf(cix)+0.5f)*CVS0 + CR0);
    f[9] = zc  - ((floorf(ciy)+0.5f)*CVS1 + CR1);
    f[10]= x - bmx; f[11]= y - bmy;
    f[12]= phi - cm0; f[13]= zc - cm1;
    f[14]= sqrtf(x*x + y*y + z*z);
    f[15]= it;
    ull acc[32];
    #pragma unroll
    for (int o = 0; o < 32; o++) acc[o] = 0ULL;
    #pragma unroll
    for (int k = 0; k < 16; k++) {
        ull v = pk2(f[k]);
        const ulonglong2* wr = (const ulonglong2*)&sw[k*64];
        #pragma unroll
        for (int m = 0; m < 16; m++) {
            ulonglong2 w = wr[m];
            ffma2(acc[2*m], v, w.x); ffma2(acc[2*m+1], v, w.y);
        }
    }
    ulonglong2* op = (ulonglong2*)&d_lin1[(size_t)i*64];
    #pragma unroll
    for (int m = 0; m < 16; m++) op[m] = make_ulonglong2(acc[2*m], acc[2*m+1]);
}

// per-channel sum/sumsq over [rows x C]
__global__ void k_stats(const float* __restrict__ data, int rows, int C, int shift, float* __restrict__ out) {
    int tid = threadIdx.x;
    int c = tid & (C-1);
    int sub = tid >> shift;
    int rpb = 256 >> shift;
    float s = 0.f, s2 = 0.f;
    for (long r = (long)blockIdx.x*rpb + sub; r < rows; r += (long)gridDim.x*rpb) {
        float v = data[(size_t)r*C + c];
        s += v; s2 += v*v;
    }
    __shared__ float sh[512];
    sh[tid] = s; sh[256+tid] = s2;
    __syncthreads();
    if (sub == 0) {
        for (int j = 1; j < rpb; j++) { s += sh[j*C + c]; s2 += sh[256 + j*C + c]; }
        atomicAdd(&out[c], s);
        atomicAdd(&out[C+c], s2);
    }
}

__global__ void k_finalize(const float* __restrict__ g, const float* __restrict__ b,
                           int C, float invn, int sbase, int bbase) {
    int c = threadIdx.x;
    if (c < C) {
        float m = d_stats[sbase+c]*invn;
        float v = d_stats[sbase+C+c]*invn - m*m;
        float a = g[c]*rsqrtf(v + 1e-3f);
        d_bn[bbase+c]   = a;
        d_bn[bbase+C+c] = b[c] - m*a;
    }
}

// lin2: 64 -> 128. Warp-uniform output quarter, 2 points per thread, f32x2.
__global__ void __launch_bounds__(256) k_lin2(const float* __restrict__ w2, int n) {
    __shared__ float sw2[64*132];
    __shared__ float sa[64], sc[64];
    int tid = threadIdx.x;
    for (int t = tid; t < 8192; t += 256) { int o = t >> 6, k = t & 63; sw2[k*132+o] = w2[t]; }
    if (tid < 64) { sa[tid] = d_bn[tid]; sc[tid] = d_bn[64+tid]; }
    __syncthreads();
    int w = tid >> 5, lane = tid & 31;
    int q = w & 3, g = w >> 2;                 // q warp-uniform -> weight LDS broadcast
    int gp = blockIdx.x*64 + g*32 + lane;
    int p0 = 2*gp;
    if (p0 >= n) return;
    bool ok1 = (p0+1) < n;
    int p1 = ok1 ? p0+1 : p0;
    const float4* h0 = (const float4*)&d_lin1[(size_t)p0*64];
    const float4* h1 = (const float4*)&d_lin1[(size_t)p1*64];
    ull acc0[16], acc1[16];
    #pragma unroll
    for (int j = 0; j < 16; j++) { acc0[j]=0ULL; acc1[j]=0ULL; }
    #pragma unroll 4
    for (int kk = 0; kk < 16; kk++) {
        float4 a = h0[kk], b = h1[kk];
        int kb = kk*4;
        float av[4] = {a.x,a.y,a.z,a.w};
        float bv[4] = {b.x,b.y,b.z,b.w};
        #pragma unroll
        for (int j = 0; j < 4; j++) {
            int k = kb + j;
            ull v0 = pk2(fmaxf(fmaf(av[j], sa[k], sc[k]), 0.f));
            ull v1 = pk2(fmaxf(fmaf(bv[j], sa[k], sc[k]), 0.f));
            const ulonglong2* wp = (const ulonglong2*)&sw2[k*132 + q*32];
            #pragma unroll
            for (int m = 0; m < 8; m++) {
                ulonglong2 wv = wp[m];
                ffma2(acc0[2*m],   v0, wv.x); ffma2(acc0[2*m+1], v0, wv.y);
                ffma2(acc1[2*m],   v1, wv.x); ffma2(acc1[2*m+1], v1, wv.y);
            }
        }
    }
    ulonglong2* o0 = (ulonglong2*)&d_lin2[(size_t)p0*128 + q*32];
    #pragma unroll
    for (int m = 0; m < 8; m++) o0[m] = make_ulonglong2(acc0[2*m], acc0[2*m+1]);
    if (ok1) {
        ulonglong2* o1 = (ulonglong2*)&d_lin2[(size_t)p1*128 + q*32];
        #pragma unroll
        for (int m = 0; m < 8; m++) o1[m] = make_ulonglong2(acc1[2*m], acc1[2*m+1]);
    }
}

// segment-max of bn_relu(lin2[:, :64]) into dense image
__global__ void k_cylmax(const float* __restrict__ pts, const float* __restrict__ cylidx, int n) {
    __shared__ float sa[64], sc[64];
    if (threadIdx.x < 64) { sa[threadIdx.x] = d_bn[128+threadIdx.x]; sc[threadIdx.x] = d_bn[256+threadIdx.x]; }
    __syncthreads();
    int i = blockIdx.x*blockDim.x + threadIdx.x;
    if (i >= n) return;
    int b = (int)pts[(size_t)i*5];
    int iy = (int)floorf(cylidx[2*(size_t)i]);   iy = max(0, min(iy, 511));
    int ix = (int)floorf(cylidx[2*(size_t)i+1]); ix = max(0, min(ix, 47));
    unsigned* dst = (unsigned*)&d_dense[(((size_t)b*512 + iy)*48 + ix)*64];
    const float4* src = (const float4*)&d_lin2[(size_t)i*128];
    #pragma unroll
    for (int j = 0; j < 16; j++) {
        float4 v = src[j];
        int c = j*4;
        float r0 = fmaxf(fmaf(v.x, sa[c+0], sc[c+0]), 0.f);
        float r1 = fmaxf(fmaf(v.y, sa[c+1], sc[c+1]), 0.f);
        float r2 = fmaxf(fmaf(v.z, sa[c+2], sc[c+2]), 0.f);
        float r3 = fmaxf(fmaf(v.w, sa[c+3], sc[c+3]), 0.f);
        atomicMax(dst+c+0, __float_as_uint(r0));
        atomicMax(dst+c+1, __float_as_uint(r1));
        atomicMax(dst+c+2, __float_as_uint(r2));
        atomicMax(dst+c+3, __float_as_uint(r3));
    }
}

// 3x3 SAME conv, 64->64: all weights resident (157KB smem), 16x8 tile, f32x2
#define CTX 16
#define CTY 8
#define HPOS ((CTY+2)*(CTX+2))        // 180
#define WPITCH 68
#define IPITCH 65
#define CONV_SMEM ((576*WPITCH + HPOS*IPITCH)*4)
__global__ void __launch_bounds__(256) k_conv(const float* __restrict__ wc) {
    extern __shared__ float dsm[];
    float* s_w  = dsm;                  // [ (cin*9+tap)*68 + f ]
    float* s_in = dsm + 576*WPITCH;     // [ pos*65 + cin ], pos = hy*18+hx
    int x0 = blockIdx.x*CTX, y0 = blockIdx.y*CTY, bb = blockIdx.z;
    int tid = threadIdx.x;
    // weights: coalesced gmem read, 4-way-conflict smem store (one-time)
    for (int t = tid; t < 36864; t += 256) {
        int f = t / 576, r = t - f*576;
        s_w[r*WPITCH + f] = wc[t];
    }
    // input halo tile
    for (int idx = tid; idx < HPOS*16; idx += 256) {
        int pos = idx >> 4, c4 = idx & 15;
        int hy = pos / (CTX+2), hx = pos - hy*(CTX+2);
        int gy = y0 + hy - 1, gx = x0 + hx - 1;
        float4 v = make_float4(0.f,0.f,0.f,0.f);
        if (gy >= 0 && gy < 512 && gx >= 0 && gx < 48)
            v = *(const float4*)&d_dense[(((size_t)bb*512 + gy)*48 + gx)*64 + c4*4];
        float* s = &s_in[pos*IPITCH + c4*4];
        s[0]=v.x; s[1]=v.y; s[2]=v.z; s[3]=v.w;
    }
    __syncthreads();
    int fs = tid >> 5;          // warp-uniform output-channel group (8 ch)
    int ps = tid & 31;
    int lyg = ps >> 4;          // 0..1 -> rows lyg*4 .. +3
    int lx  = ps & 15;
    ull acc[4][4];
    #pragma unroll
    for (int r = 0; r < 4; r++)
        #pragma unroll
        for (int j = 0; j < 4; j++) acc[r][j] = 0ULL;
    for (int cin = 0; cin < 64; cin++) {
        ull pin[6][3];
        #pragma unroll
        for (int rr = 0; rr < 6; rr++)
            #pragma unroll
            for (int cc = 0; cc < 3; cc++)
                pin[rr][cc] = pk2(s_in[((lyg*4+rr)*(CTX+2) + lx + cc)*IPITCH + cin]);
        #pragma unroll
        for (int tap = 0; tap < 9; tap++) {
            int dy = tap/3, dx = tap - dy*3;
            const ulonglong2* wp = (const ulonglong2*)&s_w[(cin*9+tap)*WPITCH + fs*8];
            ulonglong2 w0 = wp[0], w1 = wp[1];
            #pragma unroll
            for (int r = 0; r < 4; r++) {
                ull v = pin[r+dy][dx];
                ffma2(acc[r][0], v, w0.x); ffma2(acc[r][1], v, w0.y);
                ffma2(acc[r][2], v, w1.x); ffma2(acc[r][3], v, w1.y);
            }
        }
    }
    int gx = x0 + lx;
    #pragma unroll
    for (int r = 0; r < 4; r++) {
        int gy = y0 + lyg*4 + r;
        ulonglong2* o = (ulonglong2*)&d_conv[(((size_t)bb*512 + gy)*48 + gx)*64 + fs*8];
        o[0] = make_ulonglong2(acc[r][0], acc[r][1]);
        o[1] = make_ulonglong2(acc[r][2], acc[r][3]);
    }
}

// lin3: 128 -> 64. Warp-uniform output half, 2 points per thread, f32x2.
__global__ void __launch_bounds__(256) k_lin3(const float* __restrict__ pts,
        const float* __restrict__ cylidx, const float* __restrict__ w3, int n) {
    __shared__ float sw3[128*68];
    __shared__ float pa[64], pc[64], ca[64], cs[64];
    int tid = threadIdx.x;
    for (int t = tid; t < 8192; t += 256) { int o = t >> 7, k = t & 127; sw3[k*68+o] = w3[t]; }
    if (tid < 64) {
        pa[tid] = d_bn[192+tid]; pc[tid] = d_bn[320+tid];
        ca[tid] = d_bn[384+tid]; cs[tid] = d_bn[448+tid];
    }
    __syncthreads();
    int w = tid >> 5, lane = tid & 31;
    int hh = w & 1, g = w >> 1;               // hh warp-uniform
    int gp = blockIdx.x*128 + g*32 + lane;
    int p0 = 2*gp;
    if (p0 >= n) return;
    bool ok1 = (p0+1) < n;
    int p1 = ok1 ? p0+1 : p0;

    ull acc0[16], acc1[16];
    #pragma unroll
    for (int j = 0; j < 16; j++) { acc0[j]=0ULL; acc1[j]=0ULL; }

    // ---- pointwise half (k 0..63) ----
    const float4* q0 = (const float4*)&d_lin2[(size_t)p0*128 + 64];
    const float4* q1 = (const float4*)&d_lin2[(size_t)p1*128 + 64];
    #pragma unroll 2
    for (int kk = 0; kk < 16; kk++) {
        float4 a = q0[kk], b = q1[kk];
        int kb = kk*4;
        float av[4] = {a.x,a.y,a.z,a.w};
        float bv[4] = {b.x,b.y,b.z,b.w};
        #pragma unroll
        for (int j = 0; j < 4; j++) {
            int c = kb + j;
            ull v0 = pk2(fmaxf(fmaf(av[j], pa[c], pc[c]), 0.f));
            ull v1 = pk2(fmaxf(fmaf(bv[j], pa[c], pc[c]), 0.f));
            const ulonglong2* wp = (const ulonglong2*)&sw3[c*68 + hh*32];
            #pragma unroll
            for (int m = 0; m < 8; m++) {
                ulonglong2 wv = wp[m];
                ffma2(acc0[2*m],   v0, wv.x); ffma2(acc0[2*m+1], v0, wv.y);
                ffma2(acc1[2*m],   v1, wv.x); ffma2(acc1[2*m+1], v1, wv.y);
            }
        }
    }

    // ---- bilinear half (k 64..127) ----
    float wA[2], wB[2], wC[2], wD[2];
    long offA[2], offB[2], offC[2], offD[2];
    int pp[2] = {p0, p1};
    #pragma unroll
    for (int s = 0; s < 2; s++) {
        int i = pp[s];
        float yq = cylidx[2*(size_t)i], xq = cylidx[2*(size_t)i+1];
        int y0i = (int)floorf(yq); int y1i = min(y0i+1, 511); y0i = min(max(y0i,0), 511);
        int x0i = (int)floorf(xq); int x1i = min(x0i+1, 47);  x0i = min(max(x0i,0), 47);
        wA[s] = ((float)x1i - xq)*((float)y1i - yq);
        wB[s] = ((float)x1i - xq)*(yq - (float)y0i);
        wC[s] = (xq - (float)x0i)*((float)y1i - yq);
        wD[s] = (xq - (float)x0i)*(yq - (float)y0i);
        int b = (int)pts[(size_t)i*5];
        long base = (long)b*512*48*64;
        offA[s] = base + ((long)y0i*48 + x0i)*64;
        offB[s] = base + ((long)y1i*48 + x0i)*64;
        offC[s] = base + ((long)y0i*48 + x1i)*64;
        offD[s] = base + ((long)y1i*48 + x1i)*64;
    }
    #pragma unroll 2
    for (int kk = 0; kk < 16; kk++) {
        float4 A0 = *(const float4*)&d_conv[offA[0] + kk*4];
        float4 B0 = *(const float4*)&d_conv[offB[0] + kk*4];
        float4 C0 = *(const float4*)&d_conv[offC[0] + kk*4];
        float4 D0 = *(const float4*)&d_conv[offD[0] + kk*4];
        float4 A1 = *(const float4*)&d_conv[offA[1] + kk*4];
        float4 B1 = *(const float4*)&d_conv[offB[1] + kk*4];
        float4 C1 = *(const float4*)&d_conv[offC[1] + kk*4];
        float4 D1 = *(const float4*)&d_conv[offD[1] + kk*4];
        float a0v[4] = {A0.x,A0.y,A0.z,A0.w}, b0v[4] = {B0.x,B0.y,B0.z,B0.w};
        float c0v[4] = {C0.x,C0.y,C0.z,C0.w}, d0v[4] = {D0.x,D0.y,D0.z,D0.w};
        float a1v[4] = {A1.x,A1.y,A1.z,A1.w}, b1v[4] = {B1.x,B1.y,B1.z,B1.w};
        float c1v[4] = {C1.x,C1.y,C1.z,C1.w}, d1v[4] = {D1.x,D1.y,D1.z,D1.w};
        int kb = kk*4;
        #pragma unroll
        for (int j = 0; j < 4; j++) {
            int c = kb + j;
            float f0 = wA[0]*fmaxf(fmaf(a0v[j], ca[c], cs[c]), 0.f)
                     + wB[0]*fmaxf(fmaf(b0v[j], ca[c], cs[c]), 0.f)
                     + wC[0]*fmaxf(fmaf(c0v[j], ca[c], cs[c]), 0.f)
                     + wD[0]*fmaxf(fmaf(d0v[j], ca[c], cs[c]), 0.f);
            float f1 = wA[1]*fmaxf(fmaf(a1v[j], ca[c], cs[c]), 0.f)
                     + wB[1]*fmaxf(fmaf(b1v[j], ca[c], cs[c]), 0.f)
                     + wC[1]*fmaxf(fmaf(c1v[j], ca[c], cs[c]), 0.f)
                     + wD[1]*fmaxf(fmaf(d1v[j], ca[c], cs[c]), 0.f);
            ull v0 = pk2(f0), v1 = pk2(f1);
            const ulonglong2* wp = (const ulonglong2*)&sw3[(64+c)*68 + hh*32];
            #pragma unroll
            for (int m = 0; m < 8; m++) {
                ulonglong2 wv = wp[m];
                ffma2(acc0[2*m],   v0, wv.x); ffma2(acc0[2*m+1], v0, wv.y);
                ffma2(acc1[2*m],   v1, wv.x); ffma2(acc1[2*m+1], v1, wv.y);
            }
        }
    }
    ulonglong2* o0 = (ulonglong2*)&d_lin1[(size_t)p0*64 + hh*32];
    #pragma unroll
    for (int m = 0; m < 8; m++) o0[m] = make_ulonglong2(acc0[2*m], acc0[2*m+1]);
    if (ok1) {
        ulonglong2* o1 = (ulonglong2*)&d_lin1[(size_t)p1*64 + hh*32];
        #pragma unroll
        for (int m = 0; m < 8; m++) o1[m] = make_ulonglong2(acc1[2*m], acc1[2*m+1]);
    }
}

// final: bn_relu(lin3) -> out; atomicMax into bev_max region
__global__ void k_final(const int* __restrict__ binv, float* __restrict__ out, int n, int nb) {
    __shared__ float sa[64], sc[64];
    if (threadIdx.x < 64) { sa[threadIdx.x] = d_bn[512+threadIdx.x]; sc[threadIdx.x] = d_bn[576+threadIdx.x]; }
    __syncthreads();
    int i = blockIdx.x*blockDim.x + threadIdx.x;
    if (i >= n) return;
    int bi = binv[i];
    const float4* src = (const float4*)&d_lin1[(size_t)i*64];
    float4* dst = (float4*)(out + (size_t)i*64);
    unsigned* mx = (unsigned*)(out + (size_t)n*64 + (size_t)bi*64);
    #pragma unroll
    for (int j = 0; j < 16; j++) {
        float4 v = src[j];
        int c = j*4;
        float r0 = fmaxf(fmaf(v.x, sa[c+0], sc[c+0]), 0.f);
        float r1 = fmaxf(fmaf(v.y, sa[c+1], sc[c+1]), 0.f);
        float r2 = fmaxf(fmaf(v.z, sa[c+2], sc[c+2]), 0.f);
        float r3 = fmaxf(fmaf(v.w, sa[c+3], sc[c+3]), 0.f);
        dst[j] = make_float4(r0, r1, r2, r3);
        atomicMax(mx+c+0, __float_as_uint(r0));
        atomicMax(mx+c+1, __float_as_uint(r1));
        atomicMax(mx+c+2, __float_as_uint(r2));
        atomicMax(mx+c+3, __float_as_uint(r3));
    }
}

__global__ void k_voxel(const int* __restrict__ coords, float* __restrict__ out, int n, int nb) {
    int i = blockIdx.x*blockDim.x + threadIdx.x;
    if (i >= nb) return;
    int c = coords[i];
    int vb = c / 55000;
    int r  = c % 55000;
    int vx = r / 250;
    int vy = r % 250;
    float* o = out + (size_t)n*64 + (size_t)nb*64 + (size_t)i*4;
    o[0] = (float)vb; o[1] = 0.f; o[2] = (float)vy; o[3] = (float)vx;
}

// ---------------- launcher ----------------
extern "C" void kernel_launch(void* const* d_in, const int* in_sizes, int n_in,
                              void* d_out, int out_size) {
    const float* points = (const float*)d_in[0];
    const float* pcyl   = (const float*)d_in[1];
    const float* cylidx = (const float*)d_in[2];
    const float* bevidx = (const float*)d_in[3];
    const float* w1 = (const float*)d_in[4];
    const float* g1 = (const float*)d_in[5];
    const float* b1 = (const float*)d_in[6];
    const float* w2 = (const float*)d_in[7];
    const float* g2 = (const float*)d_in[8];
    const float* b2 = (const float*)d_in[9];
    const float* wc = (const float*)d_in[10];
    const float* gc = (const float*)d_in[11];
    const float* bc = (const float*)d_in[12];
    const float* w3 = (const float*)d_in[13];
    const float* g3 = (const float*)d_in[14];
    const float* b3 = (const float*)d_in[15];
    const int* binv   = (const int*)d_in[16];
    const int* bcoord = (const int*)d_in[17];
    const int* cinv   = (const int*)d_in[18];

    int n  = in_sizes[0] / 5;
    int nb = in_sizes[17];
    int nc = in_sizes[19];
    float* out = (float*)d_out;

    void *p_lin1, *p_lin2, *p_conv, *p_dense, *p_bevsum, *p_cylsum, *p_stats;
    cudaGetSymbolAddress(&p_lin1, d_lin1);
    cudaGetSymbolAddress(&p_lin2, d_lin2);
    cudaGetSymbolAddress(&p_conv, d_conv);
    cudaGetSymbolAddress(&p_dense, d_dense);
    cudaGetSymbolAddress(&p_bevsum, d_bevsum);
    cudaGetSymbolAddress(&p_cylsum, d_cylsum);
    cudaGetSymbolAddress(&p_stats, d_stats);

    static bool attr_done = false;
    if (!attr_done) {
        cudaFuncSetAttribute(k_conv, cudaFuncAttributeMaxDynamicSharedMemorySize, CONV_SMEM);
        attr_done = true;
    }

    cudaMemsetAsync(p_bevsum, 0, (size_t)nb*4*sizeof(float));
    cudaMemsetAsync(p_cylsum, 0, (size_t)nc*4*sizeof(float));
    cudaMemsetAsync(p_dense, 0, (size_t)IMG_ELEMS*sizeof(float));
    cudaMemsetAsync(p_stats, 0, 1024*sizeof(float));
    cudaMemsetAsync(out + (size_t)n*64, 0, (size_t)nb*64*sizeof(float));

    int nblk = (n + 255) / 256;
    k_scatter<<<nblk, 256>>>(points, pcyl, binv, cinv, n);
    k_lin1<<<nblk, 256>>>(points, pcyl, cylidx, bevidx, binv, cinv, w1, n);
    k_stats<<<512, 256>>>((const float*)p_lin1, n, 64, 6, (float*)p_stats + 0);
    k_finalize<<<1, 128>>>(g1, b1, 64, 1.0f/(float)n, 0, 0);
    k_lin2<<<(n + 127)/128, 256>>>(w2, n);
    k_stats<<<512, 256>>>((const float*)p_lin2, n, 128, 7, (float*)p_stats + 128);
    k_finalize<<<1, 128>>>(g2, b2, 128, 1.0f/(float)n, 128, 128);
    k_cylmax<<<nblk, 256>>>(points, cylidx, n);
    dim3 cg(3, 64, 4);
    k_conv<<<cg, 256, CONV_SMEM>>>(wc);
    k_stats<<<512, 256>>>((const float*)p_conv, 4*512*48, 64, 6, (float*)p_stats + 384);
    k_finalize<<<1, 128>>>(gc, bc, 64, 1.0f/(float)(4*512*48), 384, 384);
    k_lin3<<<(n + 255)/256, 256>>>(points, cylidx, w3, n);
    k_stats<<<512, 256>>>((const float*)p_lin1, n, 64, 6, (float*)p_stats + 512);
    k_finalize<<<1, 128>>>(g3, b3, 64, 1.0f/(float)n, 512, 512);
    k_final<<<nblk, 256>>>(binv, out, n, nb);
    k_voxel<<<(nb + 255)/256, 256>>>(bcoord, out, n, nb);
}